// round 11
// baseline (speedup 1.0000x reference)
#include <cuda_runtime.h>
#include <cstdint>

#define B_ 4
#define D_ 1024
#define N_ 2048
#define H_ 16
#define HD_ 64
#define HN_ (H_ * N_)
#define DN_ ((size_t)D_ * N_)

// Scratch (no runtime allocation allowed)
__device__ float g_Q[B_ * D_ * N_];
__device__ float g_K[B_ * D_ * N_];
__device__ float g_V[B_ * D_ * N_];
__device__ float g_X[B_ * D_ * N_];
// tf32-RNE-rounded operand copies (so cp.async + HMMA truncation == RNE)
__device__ float g_WQ[D_ * D_];
__device__ float g_WK[D_ * D_];
__device__ float g_WV[D_ * D_];
__device__ float g_WM[D_ * D_];
__device__ float g_IQ[B_ * D_ * N_];
__device__ float g_IK[B_ * D_ * N_];
__device__ float g_IV[B_ * D_ * N_];

// ===========================================================================
// Helpers
// ===========================================================================
__device__ __forceinline__ uint32_t f2tf32(float f) {
    uint32_t u;
    asm("cvt.rna.tf32.f32 %0, %1;" : "=r"(u) : "f"(f));
    return u;
}

__device__ __forceinline__ float ex2(float x) {
    float y;
    asm("ex2.approx.ftz.f32 %0, %1;" : "=f"(y) : "f"(x));
    return y;
}

__device__ __forceinline__ void mma_tf32(float c[4], const uint32_t a[4],
                                         uint32_t b0, uint32_t b1) {
    asm volatile(
        "mma.sync.aligned.m16n8k8.row.col.f32.tf32.tf32.f32 "
        "{%0,%1,%2,%3}, {%4,%5,%6,%7}, {%8,%9}, {%0,%1,%2,%3};"
        : "+f"(c[0]), "+f"(c[1]), "+f"(c[2]), "+f"(c[3])
        : "r"(a[0]), "r"(a[1]), "r"(a[2]), "r"(a[3]), "r"(b0), "r"(b1));
}

__device__ __forceinline__ uint32_t smem_u32(const void* p) {
    uint32_t a;
    asm("{ .reg .u64 t; cvta.to.shared.u64 t, %1; cvt.u32.u64 %0, t; }"
        : "=r"(a) : "l"(p));
    return a;
}

__device__ __forceinline__ void cp_async16(uint32_t dst, const void* src) {
    asm volatile("cp.async.ca.shared.global [%0], [%1], 16;"
                 :: "r"(dst), "l"(src));
}
#define CP_COMMIT() asm volatile("cp.async.commit_group;" ::: "memory")
#define CP_WAIT(n)  asm volatile("cp.async.wait_group %0;" :: "n"(n) : "memory")

// ===========================================================================
// Prep: tf32-RNE rounding, single launch.
// ===========================================================================
__global__ __launch_bounds__(256)
void round_all_kernel(float* x0, float* x1, float* x2,
                      const float* sx0, const float* sx1, const float* sx2,
                      float* w0, float* w1, float* w2, float* w3,
                      const float* sw0, const float* sw1,
                      const float* sw2, const float* sw3) {
    const int z = blockIdx.y;
    const float* s;
    float* d;
    if (z < 3) {
        s = (z == 0) ? sx0 : (z == 1) ? sx1 : sx2;
        d = (z == 0) ? x0 : (z == 1) ? x1 : x2;
    } else {
        if (blockIdx.x >= D_ * D_ / 1024) return;
        const int w = z - 3;
        s = (w == 0) ? sw0 : (w == 1) ? sw1 : (w == 2) ? sw2 : sw3;
        d = (w == 0) ? w0 : (w == 1) ? w1 : (w == 2) ? w2 : w3;
    }
    const int i = (blockIdx.x * 256 + threadIdx.x) * 4;
    float4 v = *(const float4*)(s + i);
    v.x = __uint_as_float(f2tf32(v.x));
    v.y = __uint_as_float(f2tf32(v.y));
    v.z = __uint_as_float(f2tf32(v.z));
    v.w = __uint_as_float(f2tf32(v.w));
    *(float4*)(d + i) = v;
}

// ===========================================================================
// Projection GEMM v5: 128(e) x 128(n) CTA tile, 3-stage cp.async pipeline,
// one barrier per k-tile, natural k-order fragments, 2 CTAs/SM (16 warps).
// 8 warps 2(e) x 4(n); warp tile 64x32; acc = 64 regs.
// ===========================================================================
#define P3_AS 36    // A row len 32 + pad (==4 mod 32)
#define P3_BS 136   // B row len 128 + pad (==8 mod 32)
#define P3_A_F (128 * P3_AS)          // 4608 floats
#define P3_B_F (32 * P3_BS)           // 4352 floats
#define P3_STG (P3_A_F + P3_B_F)      // 8960 floats per stage
#define P3_NSTG 3
#define P3_SMEM (P3_NSTG * P3_STG * 4)   // 107520 B -> 2 CTAs/SM

__device__ __forceinline__
void proj3_body(const float* __restrict__ W, const float* __restrict__ bias,
                const float* __restrict__ Xb, float* __restrict__ Cb,
                int n0, int e0) {
    extern __shared__ float smf[];
    const uint32_t sb = smem_u32(smf);

    const int tid  = threadIdx.x;
    const int wid  = tid >> 5;
    const int lane = tid & 31;
    const int g    = lane >> 2;
    const int tig  = lane & 3;
    const int wm   = wid >> 2;    // 0..1  (e)
    const int wn   = wid & 3;     // 0..3  (n)

    const int arow = tid >> 1;             // 0..127 (e)
    const int ak0  = (tid & 1) * 16;       // 0 or 16 (k)
    const int brow = tid >> 3;             // 0..31  (k)
    const int bcol = (tid & 7) * 16;       // n chunk base

    auto issue_stage = [&](int k0, int stg) {
        const uint32_t abase = sb + (uint32_t)(stg * P3_STG) * 4u;
        const uint32_t bbase = abase + (uint32_t)P3_A_F * 4u;
        const float* wsrc = W + (size_t)(e0 + arow) * D_ + k0 + ak0;
        const float* xsrc = Xb + (size_t)(k0 + brow) * N_ + n0 + bcol;
#pragma unroll
        for (int j = 0; j < 4; j++)
            cp_async16(abase + (uint32_t)(arow * P3_AS + ak0 + j * 4) * 4u,
                       wsrc + j * 4);
#pragma unroll
        for (int j = 0; j < 4; j++)
            cp_async16(bbase + (uint32_t)(brow * P3_BS + bcol + j * 4) * 4u,
                       xsrc + j * 4);
        CP_COMMIT();
    };

    float acc[4][4][4];
#pragma unroll
    for (int mb = 0; mb < 4; mb++)
#pragma unroll
        for (int nb = 0; nb < 4; nb++)
#pragma unroll
            for (int c = 0; c < 4; c++) acc[mb][nb][c] = 0.f;

    issue_stage(0, 0);
    issue_stage(32, 1);

    for (int c = 0; c < 32; c++) {
        const int stg = c % P3_NSTG;
        if (c + 1 < 32) { CP_WAIT(1); } else { CP_WAIT(0); }
        __syncthreads();   // stage c resident; all warps done reading stage c-1
        if (c + 2 < 32)
            issue_stage((c + 2) * 32, (c + 2) % P3_NSTG);

        const float* As = smf + stg * P3_STG;
        const float* Bs = As + P3_A_F;

#pragma unroll
        for (int ks = 0; ks < 4; ks++) {
            const int kk = ks * 8;
            uint32_t a[4][4];
#pragma unroll
            for (int mb = 0; mb < 4; mb++) {
                const int r = wm * 64 + mb * 16;
                a[mb][0] = __float_as_uint(As[(r + g) * P3_AS + kk + tig]);
                a[mb][1] = __float_as_uint(As[(r + g + 8) * P3_AS + kk + tig]);
                a[mb][2] = __float_as_uint(As[(r + g) * P3_AS + kk + tig + 4]);
                a[mb][3] = __float_as_uint(As[(r + g + 8) * P3_AS + kk + tig + 4]);
            }
#pragma unroll
            for (int nb = 0; nb < 4; nb++) {
                const int cc = wn * 32 + nb * 8 + g;
                const uint32_t b0 = __float_as_uint(Bs[(kk + tig) * P3_BS + cc]);
                const uint32_t b1 = __float_as_uint(Bs[(kk + tig + 4) * P3_BS + cc]);
#pragma unroll
                for (int mb = 0; mb < 4; mb++)
                    mma_tf32(acc[mb][nb], a[mb], b0, b1);
            }
        }
        // no trailing barrier: next iteration's barrier protects stage reuse
    }

#pragma unroll
    for (int mb = 0; mb < 4; mb++) {
        const int e  = e0 + wm * 64 + mb * 16 + g;
        const float be0 = __ldg(bias + e);
        const float be1 = __ldg(bias + e + 8);
#pragma unroll
        for (int nb = 0; nb < 4; nb++) {
            const int col = n0 + wn * 32 + nb * 8 + 2 * tig;
            float2 v0 = make_float2(acc[mb][nb][0] + be0, acc[mb][nb][1] + be0);
            float2 v1 = make_float2(acc[mb][nb][2] + be1, acc[mb][nb][3] + be1);
            *(float2*)(Cb + (size_t)e * N_ + col)       = v0;
            *(float2*)(Cb + (size_t)(e + 8) * N_ + col) = v1;
        }
    }
}

__global__ __launch_bounds__(256, 2)
void proj3_qkv_kernel(const float* __restrict__ Wq, const float* __restrict__ bq,
                      const float* __restrict__ Xq,
                      const float* __restrict__ Wk, const float* __restrict__ bk,
                      const float* __restrict__ Xk,
                      const float* __restrict__ Wv, const float* __restrict__ bv,
                      const float* __restrict__ Xv,
                      float* __restrict__ Cq, float* __restrict__ Ck,
                      float* __restrict__ Cv) {
    const int zi = blockIdx.z >> 2;
    const int b  = blockIdx.z & 3;
    const float* W    = (zi == 0) ? Wq : (zi == 1) ? Wk : Wv;
    const float* bias = (zi == 0) ? bq : (zi == 1) ? bk : bv;
    const float* X    = (zi == 0) ? Xq : (zi == 1) ? Xk : Xv;
    float* C          = (zi == 0) ? Cq : (zi == 1) ? Ck : Cv;
    proj3_body(W, bias, X + (size_t)b * DN_, C + (size_t)b * DN_,
               blockIdx.x * 128, blockIdx.y * 128);
}

__global__ __launch_bounds__(256, 2)
void proj3_out_kernel(const float* __restrict__ W, const float* __restrict__ bias,
                      const float* __restrict__ X, float* __restrict__ C) {
    const int b = blockIdx.z;
    proj3_body(W, bias, X + (size_t)b * DN_, C + (size_t)b * DN_,
               blockIdx.x * 128, blockIdx.y * 128);
}

// ===========================================================================
// Flash attention v3 (round-10 version, passing): virtual-k O-GEMM (no P
// smem round-trip), float2 V fragments, cp.async double-buffered K/V,
// one barrier per key-tile, 4 warps x 32 queries, max-free exp2 softmax.
// ===========================================================================
#define ATHR 128
#define KS_STRIDE 72
#define AVS_STRIDE 72
#define PO_STRIDE 136

#define KV_BUF_FLOATS (64 * KS_STRIDE + 64 * AVS_STRIDE)   // 9216
#define ATTN_SMEM (2 * KV_BUF_FLOATS * 4)                  // 73728 B

__global__ __launch_bounds__(ATHR, 2)
void attn_kernel(const float* __restrict__ Q, const float* __restrict__ K,
                 const float* __restrict__ V, float* __restrict__ Xo) {
    extern __shared__ float sm[];

    const int n0  = blockIdx.x * 128;
    const int h   = blockIdx.y;
    const int b   = blockIdx.z;
    const int tid = threadIdx.x;
    const int wid  = tid >> 5;
    const int lane = tid & 31;
    const int g    = lane >> 2;
    const int tig  = lane & 3;
    const int qrow = wid * 32;

    const size_t base = ((size_t)b * D_ + h) * N_;
    const uint32_t sbase = smem_u32(sm);

    auto issue_kv = [&](int m0, int buf) {
        const uint32_t kb = sbase + (uint32_t)(buf * KV_BUF_FLOATS) * 4u;
        const uint32_t vb = kb + (uint32_t)(64 * KS_STRIDE) * 4u;
#pragma unroll
        for (int it = 0; it < 8; it++) {
            const int idx = tid + it * ATHR;
            const int hd  = idx >> 4;
            const int m4  = (idx & 15) * 4;
            const size_t gaddr = base + (size_t)hd * HN_ + m0 + m4;
            cp_async16(kb + (uint32_t)(hd * KS_STRIDE + m4) * 4u, K + gaddr);
            cp_async16(vb + (uint32_t)(hd * AVS_STRIDE + m4) * 4u, V + gaddr);
        }
        CP_COMMIT();
    };

    const float SC = 0.125f * 1.44269504088896f;
    uint32_t qa[2][8][4];
#pragma unroll
    for (int bl = 0; bl < 2; bl++) {
        const int c0 = n0 + qrow + bl * 16 + g;
#pragma unroll
        for (int ksp = 0; ksp < 8; ksp++) {
            const size_t r0 = base + (size_t)(ksp * 8 + tig) * HN_;
            const size_t r1 = base + (size_t)(ksp * 8 + tig + 4) * HN_;
            qa[bl][ksp][0] = f2tf32(Q[r0 + c0] * SC);
            qa[bl][ksp][1] = f2tf32(Q[r0 + c0 + 8] * SC);
            qa[bl][ksp][2] = f2tf32(Q[r1 + c0] * SC);
            qa[bl][ksp][3] = f2tf32(Q[r1 + c0 + 8] * SC);
        }
    }

    float o[2][8][4];
    float lrow[2][2] = {{0.f, 0.f}, {0.f, 0.f}};
#pragma unroll
    for (int bl = 0; bl < 2; bl++)
#pragma unroll
        for (int nb = 0; nb < 8; nb++)
#pragma unroll
            for (int c = 0; c < 4; c++) o[bl][nb][c] = 0.f;

    issue_kv(0, 0);

    for (int mt = 0; mt < 32; mt++) {
        const int buf = mt & 1;
        CP_WAIT(0);
        __syncthreads();   // tile mt resident; all warps done with buf^1
        if (mt + 1 < 32)
            issue_kv((mt + 1) * 64, buf ^ 1);

        const float* ks = sm + buf * KV_BUF_FLOATS;
        const float* vs = ks + 64 * KS_STRIDE;

        float s[2][8][4];
#pragma unroll
        for (int bl = 0; bl < 2; bl++)
#pragma unroll
            for (int nb = 0; nb < 8; nb++)
#pragma unroll
                for (int c = 0; c < 4; c++) s[bl][nb][c] = 0.f;

#pragma unroll
        for (int ksp = 0; ksp < 8; ksp++) {
            const int kk = ksp * 8;
#pragma unroll
            for (int nb = 0; nb < 8; nb++) {
                const int key = nb * 8 + g;
                const uint32_t b0 = __float_as_uint(ks[(kk + tig) * KS_STRIDE + key]);
                const uint32_t b1 = __float_as_uint(ks[(kk + tig + 4) * KS_STRIDE + key]);
                mma_tf32(s[0][nb], qa[0][ksp], b0, b1);
                mma_tf32(s[1][nb], qa[1][ksp], b0, b1);
            }
        }

#pragma unroll
        for (int bl = 0; bl < 2; bl++)
#pragma unroll
            for (int r = 0; r < 2; r++) {
                float rs = 0.f;
#pragma unroll
                for (int nb = 0; nb < 8; nb++) {
                    float p0 = ex2(s[bl][nb][2 * r]);
                    float p1 = ex2(s[bl][nb][2 * r + 1]);
                    s[bl][nb][2 * r] = p0;
                    s[bl][nb][2 * r + 1] = p1;
                    rs += p0 + p1;
                }
                rs += __shfl_xor_sync(0xffffffffu, rs, 1);
                rs += __shfl_xor_sync(0xffffffffu, rs, 2);
                lrow[bl][r] += rs;
            }
#pragma unroll
        for (int bl = 0; bl < 2; bl++)
#pragma unroll
            for (int nb = 0; nb < 8; nb++)
#pragma unroll
                for (int c = 0; c < 4; c++)
                    s[bl][nb][c] = __uint_as_float(f2tf32(s[bl][nb][c]));

        // O += P V^T: virtual-k over keys; C-frag of S == A-frag of P
#pragma unroll
        for (int ksp = 0; ksp < 8; ksp++) {
            const int kk = ksp * 8;
            uint32_t pa[2][4];
#pragma unroll
            for (int bl = 0; bl < 2; bl++) {
                pa[bl][0] = __float_as_uint(s[bl][ksp][0]);
                pa[bl][1] = __float_as_uint(s[bl][ksp][2]);
                pa[bl][2] = __float_as_uint(s[bl][ksp][1]);
                pa[bl][3] = __float_as_uint(s[bl][ksp][3]);
            }
#pragma unroll
            for (int nb = 0; nb < 8; nb++) {
                const int hd = nb * 8 + g;
                float2 lv = *(const float2*)&vs[hd * AVS_STRIDE + kk + 2 * tig];
                const uint32_t b0 = __float_as_uint(lv.x);
                const uint32_t b1 = __float_as_uint(lv.y);
                mma_tf32(o[0][nb], pa[0], b0, b1);
                mma_tf32(o[1][nb], pa[1], b0, b1);
            }
        }
    }

    __syncthreads();   // all warps done with KV buffers before staging reuse

#pragma unroll
    for (int bl = 0; bl < 2; bl++) {
        const float rl0 = 1.f / lrow[bl][0];
        const float rl1 = 1.f / lrow[bl][1];
        const int r0 = qrow + bl * 16 + g;
#pragma unroll
        for (int nb = 0; nb < 8; nb++) {
            const int hd0 = nb * 8 + 2 * tig;
            sm[hd0 * PO_STRIDE + r0]           = __uint_as_float(f2tf32(o[bl][nb][0] * rl0));
            sm[(hd0 + 1) * PO_STRIDE + r0]     = __uint_as_float(f2tf32(o[bl][nb][1] * rl0));
            sm[hd0 * PO_STRIDE + r0 + 8]       = __uint_as_float(f2tf32(o[bl][nb][2] * rl1));
            sm[(hd0 + 1) * PO_STRIDE + r0 + 8] = __uint_as_float(f2tf32(o[bl][nb][3] * rl1));
        }
    }
    __syncthreads();

#pragma unroll
    for (int it = 0; it < 16; it++) {
        const int idx = tid + it * ATHR;
        const int hd  = idx >> 5;
        const int q4  = (idx & 31) * 4;
        float4 val = *(const float4*)&sm[hd * PO_STRIDE + q4];
        *(float4*)(Xo + base + (size_t)hd * HN_ + n0 + q4) = val;
    }
}

// ---------------------------------------------------------------------------
extern "C" void kernel_launch(void* const* d_in, const int* in_sizes, int n_in,
                              void* d_out, int out_size) {
    const float* query  = (const float*)d_in[0];
    const float* key_in = (const float*)d_in[1];
    const float* value  = (const float*)d_in[2];
    const float* Wq = (const float*)d_in[3];
    const float* bq = (const float*)d_in[4];
    const float* Wk = (const float*)d_in[5];
    const float* bk = (const float*)d_in[6];
    const float* Wv = (const float*)d_in[7];
    const float* bv = (const float*)d_in[8];
    const float* Wm = (const float*)d_in[9];
    const float* bm = (const float*)d_in[10];
    float* out = (float*)d_out;

    float *Qp, *Kp, *Vp, *Xp;
    float *WQp, *WKp, *WVp, *WMp, *IQp, *IKp, *IVp;
    cudaGetSymbolAddress((void**)&Qp, g_Q);
    cudaGetSymbolAddress((void**)&Kp, g_K);
    cudaGetSymbolAddress((void**)&Vp, g_V);
    cudaGetSymbolAddress((void**)&Xp, g_X);
    cudaGetSymbolAddress((void**)&WQp, g_WQ);
    cudaGetSymbolAddress((void**)&WKp, g_WK);
    cudaGetSymbolAddress((void**)&WVp, g_WV);
    cudaGetSymbolAddress((void**)&WMp, g_WM);
    cudaGetSymbolAddress((void**)&IQp, g_IQ);
    cudaGetSymbolAddress((void**)&IKp, g_IK);
    cudaGetSymbolAddress((void**)&IVp, g_IV);

    cudaFuncSetAttribute(proj3_qkv_kernel,
                         cudaFuncAttributeMaxDynamicSharedMemorySize, P3_SMEM);
    cudaFuncSetAttribute(proj3_out_kernel,
                         cudaFuncAttributeMaxDynamicSharedMemorySize, P3_SMEM);
    cudaFuncSetAttribute(attn_kernel,
                         cudaFuncAttributeMaxDynamicSharedMemorySize, ATTN_SMEM);

    // Prep: tf32-RNE round inputs (z 0..2) and weights (z 3..6)
    {
        dim3 gr(B_ * D_ * N_ / (256 * 4), 7);
        round_all_kernel<<<gr, 256>>>(IQp, IKp, IVp, query, key_in, value,
                                      WQp, WKp, WVp, WMp, Wq, Wk, Wv, Wm);
    }

    dim3 gq(N_ / 128, D_ / 128, 3 * B_);   // 16 x 8 x 12 — fused Q/K/V
    proj3_qkv_kernel<<<gq, 256, P3_SMEM>>>(WQp, bq, IQp, WKp, bk, IKp,
                                           WVp, bv, IVp, Qp, Kp, Vp);

    dim3 ga(N_ / 128, H_, B_);             // 16 x 16 x 4
    attn_kernel<<<ga, ATHR, ATTN_SMEM>>>(Qp, Kp, Vp, Xp);

    dim3 gp(N_ / 128, D_ / 128, B_);       // 16 x 8 x 4
    proj3_out_kernel<<<gp, 256, P3_SMEM>>>(WMp, bm, Xp, out);
}

// round 12
// speedup vs baseline: 1.2206x; 1.2206x over previous
#include <cuda_runtime.h>
#include <cstdint>

#define B_ 4
#define D_ 1024
#define N_ 2048
#define H_ 16
#define HD_ 64
#define HN_ (H_ * N_)
#define DN_ ((size_t)D_ * N_)

// Scratch (no runtime allocation allowed)
__device__ float g_Q[B_ * D_ * N_];
__device__ float g_K[B_ * D_ * N_];
__device__ float g_V[B_ * D_ * N_];
__device__ float g_X[B_ * D_ * N_];
// tf32-RNE-rounded operand copies (so cp.async + HMMA truncation == RNE)
__device__ float g_WQ[D_ * D_];
__device__ float g_WK[D_ * D_];
__device__ float g_WV[D_ * D_];
__device__ float g_WM[D_ * D_];
__device__ float g_IQ[B_ * D_ * N_];
__device__ float g_IK[B_ * D_ * N_];
__device__ float g_IV[B_ * D_ * N_];

// ===========================================================================
// Helpers
// ===========================================================================
__device__ __forceinline__ uint32_t f2tf32(float f) {
    uint32_t u;
    asm("cvt.rna.tf32.f32 %0, %1;" : "=r"(u) : "f"(f));
    return u;
}

__device__ __forceinline__ float ex2(float x) {
    float y;
    asm("ex2.approx.ftz.f32 %0, %1;" : "=f"(y) : "f"(x));
    return y;
}

__device__ __forceinline__ void mma_tf32(float c[4], const uint32_t a[4],
                                         uint32_t b0, uint32_t b1) {
    asm volatile(
        "mma.sync.aligned.m16n8k8.row.col.f32.tf32.tf32.f32 "
        "{%0,%1,%2,%3}, {%4,%5,%6,%7}, {%8,%9}, {%0,%1,%2,%3};"
        : "+f"(c[0]), "+f"(c[1]), "+f"(c[2]), "+f"(c[3])
        : "r"(a[0]), "r"(a[1]), "r"(a[2]), "r"(a[3]), "r"(b0), "r"(b1));
}

__device__ __forceinline__ uint32_t smem_u32(const void* p) {
    uint32_t a;
    asm("{ .reg .u64 t; cvta.to.shared.u64 t, %1; cvt.u32.u64 %0, t; }"
        : "=r"(a) : "l"(p));
    return a;
}

__device__ __forceinline__ void cp_async16(uint32_t dst, const void* src) {
    asm volatile("cp.async.ca.shared.global [%0], [%1], 16;"
                 :: "r"(dst), "l"(src));
}
#define CP_COMMIT() asm volatile("cp.async.commit_group;" ::: "memory")
#define CP_WAIT(n)  asm volatile("cp.async.wait_group %0;" :: "n"(n) : "memory")

// ===========================================================================
// Prep: tf32-RNE rounding, single launch.
// ===========================================================================
__global__ __launch_bounds__(256)
void round_all_kernel(float* x0, float* x1, float* x2,
                      const float* sx0, const float* sx1, const float* sx2,
                      float* w0, float* w1, float* w2, float* w3,
                      const float* sw0, const float* sw1,
                      const float* sw2, const float* sw3) {
    const int z = blockIdx.y;
    const float* s;
    float* d;
    if (z < 3) {
        s = (z == 0) ? sx0 : (z == 1) ? sx1 : sx2;
        d = (z == 0) ? x0 : (z == 1) ? x1 : x2;
    } else {
        if (blockIdx.x >= D_ * D_ / 1024) return;
        const int w = z - 3;
        s = (w == 0) ? sw0 : (w == 1) ? sw1 : (w == 2) ? sw2 : sw3;
        d = (w == 0) ? w0 : (w == 1) ? w1 : (w == 2) ? w2 : w3;
    }
    const int i = (blockIdx.x * 256 + threadIdx.x) * 4;
    float4 v = *(const float4*)(s + i);
    v.x = __uint_as_float(f2tf32(v.x));
    v.y = __uint_as_float(f2tf32(v.y));
    v.z = __uint_as_float(f2tf32(v.z));
    v.w = __uint_as_float(f2tf32(v.w));
    *(float4*)(d + i) = v;
}

// ===========================================================================
// Projection GEMM (round-9 best config): 3-stage cp.async pipeline, one
// barrier per k-tile, natural k-order fragments.
// CTA tile 128(e) x 256(n), K-tile 32; 8 warps 2(e) x 4(n); warp 64x64.
// ===========================================================================
#define P2_AS 36    // A row len 32 + pad (==4 mod 32)
#define P2_BS 264   // B row len 256 + pad (==8 mod 32)
#define P2_A_F (128 * P2_AS)          // 4608 floats
#define P2_B_F (32 * P2_BS)           // 8448 floats
#define P2_STG (P2_A_F + P2_B_F)      // 13056 floats per stage
#define P2_NSTG 3
#define P2_SMEM (P2_NSTG * P2_STG * 4)   // 156672 B

__device__ __forceinline__
void proj2_body(const float* __restrict__ W, const float* __restrict__ bias,
                const float* __restrict__ Xb, float* __restrict__ Cb,
                int n0, int e0) {
    extern __shared__ float smf[];
    const uint32_t sb = smem_u32(smf);

    const int tid  = threadIdx.x;
    const int wid  = tid >> 5;
    const int lane = tid & 31;
    const int g    = lane >> 2;
    const int tig  = lane & 3;
    const int wm   = wid >> 2;    // 0..1  (e)
    const int wn   = wid & 3;     // 0..3  (n)

    const int arow = tid >> 1;
    const int ak0  = (tid & 1) * 16;
    const int brow = tid >> 3;
    const int bch  = tid & 7;

    auto issue_stage = [&](int k0, int stg) {
        const uint32_t abase = sb + (uint32_t)(stg * P2_STG) * 4u;
        const uint32_t bbase = abase + (uint32_t)P2_A_F * 4u;
        const float* wsrc = W + (size_t)(e0 + arow) * D_ + k0 + ak0;
        const float* xsrc = Xb + (size_t)(k0 + brow) * N_ + n0;
#pragma unroll
        for (int j = 0; j < 4; j++)
            cp_async16(abase + (uint32_t)(arow * P2_AS + ak0 + j * 4) * 4u,
                       wsrc + j * 4);
#pragma unroll
        for (int j = 0; j < 8; j++) {
            const int c4 = (bch + j * 8) * 4;
            cp_async16(bbase + (uint32_t)(brow * P2_BS + c4) * 4u, xsrc + c4);
        }
        CP_COMMIT();
    };

    float acc[4][8][4];
#pragma unroll
    for (int mb = 0; mb < 4; mb++)
#pragma unroll
        for (int nb = 0; nb < 8; nb++)
#pragma unroll
            for (int c = 0; c < 4; c++) acc[mb][nb][c] = 0.f;

    issue_stage(0, 0);
    issue_stage(32, 1);

    for (int c = 0; c < 32; c++) {
        const int stg = c % P2_NSTG;
        if (c + 1 < 32) { CP_WAIT(1); } else { CP_WAIT(0); }
        __syncthreads();   // stage c resident; all warps done reading stage c-1
        if (c + 2 < 32)
            issue_stage((c + 2) * 32, (c + 2) % P2_NSTG);

        const float* As = smf + stg * P2_STG;
        const float* Bs = As + P2_A_F;

#pragma unroll
        for (int ks = 0; ks < 4; ks++) {
            const int kk = ks * 8;
            uint32_t a[4][4];
#pragma unroll
            for (int mb = 0; mb < 4; mb++) {
                const int r = wm * 64 + mb * 16;
                a[mb][0] = __float_as_uint(As[(r + g) * P2_AS + kk + tig]);
                a[mb][1] = __float_as_uint(As[(r + g + 8) * P2_AS + kk + tig]);
                a[mb][2] = __float_as_uint(As[(r + g) * P2_AS + kk + tig + 4]);
                a[mb][3] = __float_as_uint(As[(r + g + 8) * P2_AS + kk + tig + 4]);
            }
#pragma unroll
            for (int nb = 0; nb < 8; nb++) {
                const int cc = wn * 64 + nb * 8 + g;
                const uint32_t b0 = __float_as_uint(Bs[(kk + tig) * P2_BS + cc]);
                const uint32_t b1 = __float_as_uint(Bs[(kk + tig + 4) * P2_BS + cc]);
#pragma unroll
                for (int mb = 0; mb < 4; mb++)
                    mma_tf32(acc[mb][nb], a[mb], b0, b1);
            }
        }
        // no trailing barrier: next iteration's barrier protects stage reuse
    }

#pragma unroll
    for (int mb = 0; mb < 4; mb++) {
        const int e  = e0 + wm * 64 + mb * 16 + g;
        const float be0 = __ldg(bias + e);
        const float be1 = __ldg(bias + e + 8);
#pragma unroll
        for (int nb = 0; nb < 8; nb++) {
            const int col = n0 + wn * 64 + nb * 8 + 2 * tig;
            float2 v0 = make_float2(acc[mb][nb][0] + be0, acc[mb][nb][1] + be0);
            float2 v1 = make_float2(acc[mb][nb][2] + be1, acc[mb][nb][3] + be1);
            *(float2*)(Cb + (size_t)e * N_ + col)       = v0;
            *(float2*)(Cb + (size_t)(e + 8) * N_ + col) = v1;
        }
    }
}

__global__ __launch_bounds__(256, 1)
void proj2_qkv_kernel(const float* __restrict__ Wq, const float* __restrict__ bq,
                      const float* __restrict__ Xq,
                      const float* __restrict__ Wk, const float* __restrict__ bk,
                      const float* __restrict__ Xk,
                      const float* __restrict__ Wv, const float* __restrict__ bv,
                      const float* __restrict__ Xv,
                      float* __restrict__ Cq, float* __restrict__ Ck,
                      float* __restrict__ Cv) {
    const int zi = blockIdx.z >> 2;
    const int b  = blockIdx.z & 3;
    const float* W    = (zi == 0) ? Wq : (zi == 1) ? Wk : Wv;
    const float* bias = (zi == 0) ? bq : (zi == 1) ? bk : bv;
    const float* X    = (zi == 0) ? Xq : (zi == 1) ? Xk : Xv;
    float* C          = (zi == 0) ? Cq : (zi == 1) ? Ck : Cv;
    proj2_body(W, bias, X + (size_t)b * DN_, C + (size_t)b * DN_,
               blockIdx.x * 256, blockIdx.y * 128);
}

__global__ __launch_bounds__(256, 1)
void proj2_out_kernel(const float* __restrict__ W, const float* __restrict__ bias,
                      const float* __restrict__ X, float* __restrict__ C) {
    const int b = blockIdx.z;
    proj2_body(W, bias, X + (size_t)b * DN_, C + (size_t)b * DN_,
               blockIdx.x * 256, blockIdx.y * 128);
}

// ===========================================================================
// Flash attention v3 (round-10 version, best measured): virtual-k O-GEMM
// (no P smem round-trip), float2 V fragments, cp.async double-buffered K/V,
// one barrier per key-tile, 4 warps x 32 queries, max-free exp2 softmax.
// ===========================================================================
#define ATHR 128
#define KS_STRIDE 72
#define AVS_STRIDE 72
#define PO_STRIDE 136

#define KV_BUF_FLOATS (64 * KS_STRIDE + 64 * AVS_STRIDE)   // 9216
#define ATTN_SMEM (2 * KV_BUF_FLOATS * 4)                  // 73728 B

__global__ __launch_bounds__(ATHR, 2)
void attn_kernel(const float* __restrict__ Q, const float* __restrict__ K,
                 const float* __restrict__ V, float* __restrict__ Xo) {
    extern __shared__ float sm[];

    const int n0  = blockIdx.x * 128;
    const int h   = blockIdx.y;
    const int b   = blockIdx.z;
    const int tid = threadIdx.x;
    const int wid  = tid >> 5;
    const int lane = tid & 31;
    const int g    = lane >> 2;
    const int tig  = lane & 3;
    const int qrow = wid * 32;

    const size_t base = ((size_t)b * D_ + h) * N_;
    const uint32_t sbase = smem_u32(sm);

    auto issue_kv = [&](int m0, int buf) {
        const uint32_t kb = sbase + (uint32_t)(buf * KV_BUF_FLOATS) * 4u;
        const uint32_t vb = kb + (uint32_t)(64 * KS_STRIDE) * 4u;
#pragma unroll
        for (int it = 0; it < 8; it++) {
            const int idx = tid + it * ATHR;
            const int hd  = idx >> 4;
            const int m4  = (idx & 15) * 4;
            const size_t gaddr = base + (size_t)hd * HN_ + m0 + m4;
            cp_async16(kb + (uint32_t)(hd * KS_STRIDE + m4) * 4u, K + gaddr);
            cp_async16(vb + (uint32_t)(hd * AVS_STRIDE + m4) * 4u, V + gaddr);
        }
        CP_COMMIT();
    };

    const float SC = 0.125f * 1.44269504088896f;
    uint32_t qa[2][8][4];
#pragma unroll
    for (int bl = 0; bl < 2; bl++) {
        const int c0 = n0 + qrow + bl * 16 + g;
#pragma unroll
        for (int ksp = 0; ksp < 8; ksp++) {
            const size_t r0 = base + (size_t)(ksp * 8 + tig) * HN_;
            const size_t r1 = base + (size_t)(ksp * 8 + tig + 4) * HN_;
            qa[bl][ksp][0] = f2tf32(Q[r0 + c0] * SC);
            qa[bl][ksp][1] = f2tf32(Q[r0 + c0 + 8] * SC);
            qa[bl][ksp][2] = f2tf32(Q[r1 + c0] * SC);
            qa[bl][ksp][3] = f2tf32(Q[r1 + c0 + 8] * SC);
        }
    }

    float o[2][8][4];
    float lrow[2][2] = {{0.f, 0.f}, {0.f, 0.f}};
#pragma unroll
    for (int bl = 0; bl < 2; bl++)
#pragma unroll
        for (int nb = 0; nb < 8; nb++)
#pragma unroll
            for (int c = 0; c < 4; c++) o[bl][nb][c] = 0.f;

    issue_kv(0, 0);

    for (int mt = 0; mt < 32; mt++) {
        const int buf = mt & 1;
        CP_WAIT(0);
        __syncthreads();   // tile mt resident; all warps done with buf^1
        if (mt + 1 < 32)
            issue_kv((mt + 1) * 64, buf ^ 1);

        const float* ks = sm + buf * KV_BUF_FLOATS;
        const float* vs = ks + 64 * KS_STRIDE;

        float s[2][8][4];
#pragma unroll
        for (int bl = 0; bl < 2; bl++)
#pragma unroll
            for (int nb = 0; nb < 8; nb++)
#pragma unroll
                for (int c = 0; c < 4; c++) s[bl][nb][c] = 0.f;

#pragma unroll
        for (int ksp = 0; ksp < 8; ksp++) {
            const int kk = ksp * 8;
#pragma unroll
            for (int nb = 0; nb < 8; nb++) {
                const int key = nb * 8 + g;
                const uint32_t b0 = __float_as_uint(ks[(kk + tig) * KS_STRIDE + key]);
                const uint32_t b1 = __float_as_uint(ks[(kk + tig + 4) * KS_STRIDE + key]);
                mma_tf32(s[0][nb], qa[0][ksp], b0, b1);
                mma_tf32(s[1][nb], qa[1][ksp], b0, b1);
            }
        }

#pragma unroll
        for (int bl = 0; bl < 2; bl++)
#pragma unroll
            for (int r = 0; r < 2; r++) {
                float rs = 0.f;
#pragma unroll
                for (int nb = 0; nb < 8; nb++) {
                    float p0 = ex2(s[bl][nb][2 * r]);
                    float p1 = ex2(s[bl][nb][2 * r + 1]);
                    s[bl][nb][2 * r] = p0;
                    s[bl][nb][2 * r + 1] = p1;
                    rs += p0 + p1;
                }
                rs += __shfl_xor_sync(0xffffffffu, rs, 1);
                rs += __shfl_xor_sync(0xffffffffu, rs, 2);
                lrow[bl][r] += rs;
            }
#pragma unroll
        for (int bl = 0; bl < 2; bl++)
#pragma unroll
            for (int nb = 0; nb < 8; nb++)
#pragma unroll
                for (int c = 0; c < 4; c++)
                    s[bl][nb][c] = __uint_as_float(f2tf32(s[bl][nb][c]));

        // O += P V^T: virtual-k over keys; C-frag of S == A-frag of P
#pragma unroll
        for (int ksp = 0; ksp < 8; ksp++) {
            const int kk = ksp * 8;
            uint32_t pa[2][4];
#pragma unroll
            for (int bl = 0; bl < 2; bl++) {
                pa[bl][0] = __float_as_uint(s[bl][ksp][0]);
                pa[bl][1] = __float_as_uint(s[bl][ksp][2]);
                pa[bl][2] = __float_as_uint(s[bl][ksp][1]);
                pa[bl][3] = __float_as_uint(s[bl][ksp][3]);
            }
#pragma unroll
            for (int nb = 0; nb < 8; nb++) {
                const int hd = nb * 8 + g;
                float2 lv = *(const float2*)&vs[hd * AVS_STRIDE + kk + 2 * tig];
                const uint32_t b0 = __float_as_uint(lv.x);
                const uint32_t b1 = __float_as_uint(lv.y);
                mma_tf32(o[0][nb], pa[0], b0, b1);
                mma_tf32(o[1][nb], pa[1], b0, b1);
            }
        }
    }

    __syncthreads();   // all warps done with KV buffers before staging reuse

#pragma unroll
    for (int bl = 0; bl < 2; bl++) {
        const float rl0 = 1.f / lrow[bl][0];
        const float rl1 = 1.f / lrow[bl][1];
        const int r0 = qrow + bl * 16 + g;
#pragma unroll
        for (int nb = 0; nb < 8; nb++) {
            const int hd0 = nb * 8 + 2 * tig;
            sm[hd0 * PO_STRIDE + r0]           = __uint_as_float(f2tf32(o[bl][nb][0] * rl0));
            sm[(hd0 + 1) * PO_STRIDE + r0]     = __uint_as_float(f2tf32(o[bl][nb][1] * rl0));
            sm[hd0 * PO_STRIDE + r0 + 8]       = __uint_as_float(f2tf32(o[bl][nb][2] * rl1));
            sm[(hd0 + 1) * PO_STRIDE + r0 + 8] = __uint_as_float(f2tf32(o[bl][nb][3] * rl1));
        }
    }
    __syncthreads();

#pragma unroll
    for (int it = 0; it < 16; it++) {
        const int idx = tid + it * ATHR;
        const int hd  = idx >> 5;
        const int q4  = (idx & 31) * 4;
        float4 val = *(const float4*)&sm[hd * PO_STRIDE + q4];
        *(float4*)(Xo + base + (size_t)hd * HN_ + n0 + q4) = val;
    }
}

// ---------------------------------------------------------------------------
extern "C" void kernel_launch(void* const* d_in, const int* in_sizes, int n_in,
                              void* d_out, int out_size) {
    const float* query  = (const float*)d_in[0];
    const float* key_in = (const float*)d_in[1];
    const float* value  = (const float*)d_in[2];
    const float* Wq = (const float*)d_in[3];
    const float* bq = (const float*)d_in[4];
    const float* Wk = (const float*)d_in[5];
    const float* bk = (const float*)d_in[6];
    const float* Wv = (const float*)d_in[7];
    const float* bv = (const float*)d_in[8];
    const float* Wm = (const float*)d_in[9];
    const float* bm = (const float*)d_in[10];
    float* out = (float*)d_out;

    float *Qp, *Kp, *Vp, *Xp;
    float *WQp, *WKp, *WVp, *WMp, *IQp, *IKp, *IVp;
    cudaGetSymbolAddress((void**)&Qp, g_Q);
    cudaGetSymbolAddress((void**)&Kp, g_K);
    cudaGetSymbolAddress((void**)&Vp, g_V);
    cudaGetSymbolAddress((void**)&Xp, g_X);
    cudaGetSymbolAddress((void**)&WQp, g_WQ);
    cudaGetSymbolAddress((void**)&WKp, g_WK);
    cudaGetSymbolAddress((void**)&WVp, g_WV);
    cudaGetSymbolAddress((void**)&WMp, g_WM);
    cudaGetSymbolAddress((void**)&IQp, g_IQ);
    cudaGetSymbolAddress((void**)&IKp, g_IK);
    cudaGetSymbolAddress((void**)&IVp, g_IV);

    cudaFuncSetAttribute(proj2_qkv_kernel,
                         cudaFuncAttributeMaxDynamicSharedMemorySize, P2_SMEM);
    cudaFuncSetAttribute(proj2_out_kernel,
                         cudaFuncAttributeMaxDynamicSharedMemorySize, P2_SMEM);
    cudaFuncSetAttribute(attn_kernel,
                         cudaFuncAttributeMaxDynamicSharedMemorySize, ATTN_SMEM);

    // Prep: tf32-RNE round inputs (z 0..2) and weights (z 3..6)
    {
        dim3 gr(B_ * D_ * N_ / (256 * 4), 7);
        round_all_kernel<<<gr, 256>>>(IQp, IKp, IVp, query, key_in, value,
                                      WQp, WKp, WVp, WMp, Wq, Wk, Wv, Wm);
    }

    dim3 gq(N_ / 256, D_ / 128, 3 * B_);   // 8 x 8 x 12 — fused Q/K/V
    proj2_qkv_kernel<<<gq, 256, P2_SMEM>>>(WQp, bq, IQp, WKp, bk, IKp,
                                           WVp, bv, IVp, Qp, Kp, Vp);

    dim3 ga(N_ / 128, H_, B_);             // 16 x 16 x 4
    attn_kernel<<<ga, ATHR, ATTN_SMEM>>>(Qp, Kp, Vp, Xp);

    dim3 gp(N_ / 256, D_ / 128, B_);       // 8 x 8 x 4
    proj2_out_kernel<<<gp, 256, P2_SMEM>>>(WMp, bm, Xp, out);
}